// round 17
// baseline (speedup 1.0000x reference)
#include <cuda_runtime.h>
#include <cstdint>
#include <math.h>

#define N_TOK 16384
#define DDIM  2048
#define NEXP  64
#define TOPK  8
#define BM    64
#define KC    32
#define NC    (DDIM/KC)
#define THREADS 256
#define NSTAGE 3

#define A_STRIDE 36
#define B_STRIDE 72
#define A_TILE_W (BM*A_STRIDE)             // 2304 words per stage
#define B_TILE_W (KC*B_STRIDE)             // 2304 words per stage
#define A_RAW(st) ((st)*A_TILE_W)
#define B_RAW(st) (NSTAGE*A_TILE_W + (st)*B_TILE_W)
#define SM_WORDS (NSTAGE*(A_TILE_W + B_TILE_W))   // 13824
#define SM_BYTES (SM_WORDS*4)                     // 55296

// post-GEMM smem carve (word offsets, reuse A region)
#define SS_OFF    0                         // Ss[64][65] = 4160 words
#define FLAGC_OFF 4160
#define FLAGL_OFF 4162                      // 64 ints
#define PART_OFF  4228                      // 512 floats [64 exp][8 sc]
#define EXACT_OFF 4740                      // 64 floats

static __device__ __forceinline__ uint32_t tf32r(float v) {
    uint32_t u; asm("cvt.rna.tf32.f32 %0, %1;" : "=r"(u) : "f"(v));
    return u;
}
static __device__ __forceinline__ uint32_t smem_u32(const void* p) {
    uint32_t a;
    asm("{ .reg .u64 t; cvta.to.shared.u64 t, %1; cvt.u32.u64 %0, t; }" : "=r"(a) : "l"(p));
    return a;
}
static __device__ __forceinline__ void cp16(uint32_t dst, const void* src) {
    asm volatile("cp.async.cg.shared.global [%0], [%1], 16;" :: "r"(dst), "l"(src));
}
#define CP_COMMIT() asm volatile("cp.async.commit_group;" ::: "memory")
#define CP_WAIT(n)  asm volatile("cp.async.wait_group %0;" :: "n"(n) : "memory")

#define MMA_TF32(d, a, b) \
    asm("mma.sync.aligned.m16n8k8.row.col.f32.tf32.tf32.f32 " \
        "{%0,%1,%2,%3}, {%4,%5,%6,%7}, {%8,%9}, {%0,%1,%2,%3};" \
        : "+f"((d)[0]), "+f"((d)[1]), "+f"((d)[2]), "+f"((d)[3]) \
        : "r"((a)[0]), "r"((a)[1]), "r"((a)[2]), "r"((a)[3]), \
          "r"((b)[0]), "r"((b)[1]))

__global__ __launch_bounds__(THREADS, 2)
void noisyk_gate_mma(const float* __restrict__ x,
                     const float* __restrict__ W,
                     const float* __restrict__ bias,
                     float* __restrict__ g_out,
                     float* __restrict__ idx_out,
                     float* __restrict__ sc_out)
{
    extern __shared__ __align__(16) uint32_t smw[];
    float* Ss = (float*)(smw + SS_OFF);
    const uint32_t smb = smem_u32(smw);

    const int tid = threadIdx.x;
    const int w   = tid >> 5;
    const int l   = tid & 31;
    const int g   = l >> 2;                 // 0..7
    const int t   = l & 3;                  // 0..3
    const int tokW = 16 * (w & 3);          // warp token base
    const int nW   = 32 * (w >> 2);         // warp expert half base
    const int tokRow = blockIdx.x * BM;

    // staging maps (raw copies, 16B each)
    // A: c = tid + 256j -> tok = c>>3, koff = (c&7)*4
    // B: c = tid + 256j -> bk  = c>>4, bne  = (c&15)*4
    const int a_tok0 = tid >> 3,  a_ko0 = (tid & 7) * 4;
    const int a_tok1 = (tid + 256) >> 3, a_ko1 = ((tid + 256) & 7) * 4;
    const int b_k0 = tid >> 4,   b_ne0 = (tid & 15) * 4;
    const int b_k1 = (tid + 256) >> 4, b_ne1 = ((tid + 256) & 15) * 4;

    // ---- prologue: async-stage chunks 0 and 1 ----
    #pragma unroll
    for (int st = 0; st < 2; st++) {
        const int kb = st * KC;
        cp16(smb + (A_RAW(st) + a_tok0 * A_STRIDE + a_ko0) * 4,
             x + (size_t)(tokRow + a_tok0) * DDIM + kb + a_ko0);
        cp16(smb + (A_RAW(st) + a_tok1 * A_STRIDE + a_ko1) * 4,
             x + (size_t)(tokRow + a_tok1) * DDIM + kb + a_ko1);
        cp16(smb + (B_RAW(st) + b_k0 * B_STRIDE + b_ne0) * 4,
             W + (size_t)(kb + b_k0) * NEXP + b_ne0);
        cp16(smb + (B_RAW(st) + b_k1 * B_STRIDE + b_ne1) * 4,
             W + (size_t)(kb + b_k1) * NEXP + b_ne1);
        CP_COMMIT();
    }

    float acc_hh[4][4], acc_sm[4][4];
    #pragma unroll
    for (int ni = 0; ni < 4; ni++)
        #pragma unroll
        for (int q = 0; q < 4; q++) { acc_hh[ni][q] = 0.0f; acc_sm[ni][q] = 0.0f; }

    for (int kt = 0; kt < NC; ++kt) {
        // chunk kt's copy must be complete (1 newer group may remain in flight)
        if (kt + 1 < NC) { CP_WAIT(1); } else { CP_WAIT(0); }
        __syncthreads();

        // issue chunk kt+2 into ring stage (kt+2)%3 (that buffer was consumed
        // in iteration kt-1; the barrier above ordered it)
        if (kt + 2 < NC) {
            const int st = (kt + 2) % NSTAGE;
            const int kb = (kt + 2) * KC;
            cp16(smb + (A_RAW(st) + a_tok0 * A_STRIDE + a_ko0) * 4,
                 x + (size_t)(tokRow + a_tok0) * DDIM + kb + a_ko0);
            cp16(smb + (A_RAW(st) + a_tok1 * A_STRIDE + a_ko1) * 4,
                 x + (size_t)(tokRow + a_tok1) * DDIM + kb + a_ko1);
            cp16(smb + (B_RAW(st) + b_k0 * B_STRIDE + b_ne0) * 4,
                 W + (size_t)(kb + b_k0) * NEXP + b_ne0);
            cp16(smb + (B_RAW(st) + b_k1 * B_STRIDE + b_ne1) * 4,
                 W + (size_t)(kb + b_k1) * NEXP + b_ne1);
            CP_COMMIT();
        }

        // ---- compute chunk kt from ring stage kt%3 (split at read) ----
        const int st = kt % NSTAGE;
        const float* Ar = (const float*)&smw[A_RAW(st)];
        const float* Br = (const float*)&smw[B_RAW(st)];

        #pragma unroll
        for (int s = 0; s < 4; ++s) {
            const int k0 = s * 8;
            uint32_t a_h[4], a_l[4];
            #pragma unroll
            for (int c = 0; c < 4; c++) {
                const int row = tokW + g + ((c & 1) << 3);
                const int col = k0 + t + ((c >> 1) << 2);
                float v = Ar[row * A_STRIDE + col];
                a_h[c] = tf32r(v);
                a_l[c] = tf32r(v - __uint_as_float(a_h[c]));
            }
            uint32_t b_h[8], b_l[8];
            #pragma unroll
            for (int ni = 0; ni < 4; ni++) {
                #pragma unroll
                for (int cb = 0; cb < 2; cb++) {
                    const int row = k0 + t + (cb << 2);
                    const int col = nW + ni * 8 + g;
                    float wv = Br[row * B_STRIDE + col];
                    const int slot = ni * 2 + cb;
                    b_h[slot] = tf32r(wv);
                    b_l[slot] = tf32r(wv - __uint_as_float(b_h[slot]));
                }
            }
            #pragma unroll
            for (int ni = 0; ni < 4; ni++) {
                MMA_TF32(acc_hh[ni], a_h, &b_h[ni * 2]);
                MMA_TF32(acc_sm[ni], a_h, &b_l[ni * 2]);
                MMA_TF32(acc_sm[ni], a_l, &b_h[ni * 2]);
            }
        }
    }
    __syncthreads();

    // ---- epilogue: bias + sigmoid, scores ----
    #pragma unroll
    for (int ni = 0; ni < 4; ni++) {
        const int r0 = tokW + g;
        const int r1 = r0 + 8;
        const int c0 = nW + ni * 8 + 2 * t;
        const float b0 = bias[c0], b1 = bias[c0 + 1];
        float z[4] = {(acc_hh[ni][0] + acc_sm[ni][0]) + b0,
                      (acc_hh[ni][1] + acc_sm[ni][1]) + b1,
                      (acc_hh[ni][2] + acc_sm[ni][2]) + b0,
                      (acc_hh[ni][3] + acc_sm[ni][3]) + b1};
        float s[4];
        #pragma unroll
        for (int q = 0; q < 4; q++) {
            if (z[q] >= 0.0f) s[q] = 1.0f / (1.0f + expf(-z[q]));
            else { float e = expf(z[q]); s[q] = e / (1.0f + e); }
        }
        Ss[r0 * 65 + c0]     = s[0];
        Ss[r0 * 65 + c0 + 1] = s[1];
        Ss[r1 * 65 + c0]     = s[2];
        Ss[r1 * 65 + c0 + 1] = s[3];
        *(float2*)(sc_out + (size_t)(tokRow + r0) * NEXP + c0) = make_float2(s[0], s[1]);
        *(float2*)(sc_out + (size_t)(tokRow + r1) * NEXP + c0) = make_float2(s[2], s[3]);
    }

    int* flagcnt  = (int*)(smw + FLAGC_OFF);
    int* flaglist = (int*)(smw + FLAGL_OFF);
    if (tid == 0) *flagcnt = 0;
    __syncthreads();

    // ---- top-9 per token; flag knife-edge tokens ----
    if (tid < BM) {
        float vals[9];
        int   ids[9];
        #pragma unroll
        for (int j = 0; j < 9; j++) { vals[j] = -1e30f; ids[j] = 0; }
        for (int e = 0; e < NEXP; e++) {
            float sv = Ss[tid * 65 + e];
            if (sv > vals[8]) {
                int p = 8;
                while (p > 0 && sv > vals[p - 1]) {
                    vals[p] = vals[p - 1]; ids[p] = ids[p - 1]; p--;
                }
                vals[p] = sv; ids[p] = e;
            }
        }
        bool knife = false;
        #pragma unroll
        for (int j = 0; j < 8; j++)
            if (vals[j] - vals[j + 1] < 1e-5f) knife = true;

        if (!knife) {
            float sum = 0.0f;
            #pragma unroll
            for (int j = 0; j < TOPK; j++) sum += vals[j];
            const float inv = 1.0f / sum;
            const size_t base = (size_t)(tokRow + tid) * TOPK;
            #pragma unroll
            for (int j = 0; j < TOPK; j++) {
                g_out[base + j]   = vals[j] * inv;
                idx_out[base + j] = (float)ids[j];
            }
        } else {
            int pos = atomicAdd(flagcnt, 1);
            flaglist[pos] = tid;
        }
    }
    __syncthreads();

    // ---- flagged tokens: bit-exact R5-order replay (64 exp x 4 threads,
    //      each thread does 2 superchunks sequentially; strict left folds) ----
    const int nflag = *flagcnt;
    float* part   = (float*)(smw + PART_OFF);   // [64 exp][8 sc]
    float* exactf = (float*)(smw + EXACT_OFF);  // [64]
    for (int i = 0; i < nflag; i++) {
        const int tok = flaglist[i];
        {
            const int e = tid & 63;
            const int h = tid >> 6;              // 0..3
            const float* xr = x + (size_t)(tokRow + tok) * DDIM;
            const float* wp = W + e;
            #pragma unroll
            for (int hs = 0; hs < 2; hs++) {
                const int sc = 2 * h + hs;
                float sup = 0.0f;
                for (int t2 = 0; t2 < 16; t2++) {
                    const int k0 = sc * 256 + t2 * 16;
                    float tile = __fmul_rn(xr[k0], wp[(size_t)k0 * NEXP]);
                    #pragma unroll
                    for (int kk = 1; kk < 16; kk++)
                        tile = __fmaf_rn(xr[k0 + kk], wp[(size_t)(k0 + kk) * NEXP], tile);
                    sup = (t2 == 0) ? tile : __fadd_rn(sup, tile);
                }
                part[e * 8 + sc] = sup;
            }
        }
        __syncthreads();
        if (tid < NEXP) {
            float grand = part[tid * 8 + 0];
            #pragma unroll
            for (int sc = 1; sc < 8; sc++)
                grand = __fadd_rn(grand, part[tid * 8 + sc]);
            float z = grand + bias[tid];
            float s;
            if (z >= 0.0f) {
                s = 1.0f / (1.0f + expf(-z));
            } else {
                float e2 = expf(z);
                s = e2 / (1.0f + e2);
            }
            exactf[tid] = s;
        }
        __syncthreads();
        if (tid == 0) {
            float vals[TOPK];
            int   ids[TOPK];
            #pragma unroll
            for (int j = 0; j < TOPK; j++) { vals[j] = -1e30f; ids[j] = 0; }
            for (int e2 = 0; e2 < NEXP; e2++) {
                float sv = exactf[e2];
                if (sv > vals[TOPK - 1]) {
                    int p = TOPK - 1;
                    while (p > 0 && sv > vals[p - 1]) {
                        vals[p] = vals[p - 1]; ids[p] = ids[p - 1]; p--;
                    }
                    vals[p] = sv; ids[p] = e2;
                }
            }
            float sum = 0.0f;
            #pragma unroll
            for (int j = 0; j < TOPK; j++) sum += vals[j];
            const float inv = 1.0f / sum;
            const size_t base = (size_t)(tokRow + tok) * TOPK;
            #pragma unroll
            for (int j = 0; j < TOPK; j++) {
                g_out[base + j]   = vals[j] * inv;
                idx_out[base + j] = (float)ids[j];
            }
        }
        __syncthreads();
    }
}

extern "C" void kernel_launch(void* const* d_in, const int* in_sizes, int n_in,
                              void* d_out, int out_size)
{
    const float* x = (const float*)d_in[0];
    const float* W = (const float*)d_in[1];
    const float* b = (const float*)d_in[2];

    float* out     = (float*)d_out;
    float* g_out   = out;
    float* idx_out = out + (size_t)N_TOK * TOPK;
    float* sc_out  = out + (size_t)2 * N_TOK * TOPK;

    cudaFuncSetAttribute(noisyk_gate_mma,
                         cudaFuncAttributeMaxDynamicSharedMemorySize, SM_BYTES);
    noisyk_gate_mma<<<N_TOK / BM, THREADS, SM_BYTES>>>(x, W, b, g_out, idx_out, sc_out);
}